// round 2
// baseline (speedup 1.0000x reference)
#include <cuda_runtime.h>
#include <math.h>

// Problem constants
#define BATCH   4
#define SEQ     1024
#define HID     4096
#define NQH     32
#define NKV     8
#define HD      128
#define QKV_N   6144                 // (NQH + 2*NKV) * HD
#define BS_ROWS 4096                 // BATCH * SEQ

// Scratch (allocation-free rule: __device__ globals, referenced directly)
__device__ float g_qkv[(size_t)BS_ROWS * QKV_N];   // [B*S, 6144]  (q | k | v)
__device__ float g_attn[(size_t)BS_ROWS * HID];    // [B*S, 4096]  attention output

// ---------------------------------------------------------------------------
// SGEMM: C[M,N] = A[M,K] @ B[K,N], all row-major, fp32.
// 128x128 block tile, BK=16, 256 threads, 8x8 per-thread microtile,
// double-buffered shared memory, float4 global loads.
// Dims are always multiples of 128/16 here -> no bounds checks.
// ---------------------------------------------------------------------------
__global__ __launch_bounds__(256, 2)
void sgemm128(const float* __restrict__ A, const float* __restrict__ Bm,
              float* __restrict__ C, int M, int N, int K) {
    __shared__ float As[2][16][132];   // A tile stored transposed [k][m], padded
    __shared__ float Bs[2][16][128];   // B tile [k][n]

    const int tid = threadIdx.x;
    const int ty  = tid >> 4;          // 0..15 (row group)
    const int tx  = tid & 15;          // 0..15 (col group)
    const long bm = (long)blockIdx.y * 128;
    const long bn = (long)blockIdx.x * 128;

    // Global load mapping
    const int arow = tid >> 2;         // 0..63  (+64 for second half)
    const int acol = (tid & 3) << 2;   // 0,4,8,12
    const int brow = tid >> 5;         // 0..7   (+8 for second half)
    const int bcol = (tid & 31) << 2;  // 0..124

    const float* Ap = A  + (bm + arow) * (long)K + acol;
    const float* Bp = Bm + (long)brow * N + bn + bcol;
    const long AHalf = 64L * K;
    const long BHalf = 8L * N;

    float acc[8][8];
#pragma unroll
    for (int i = 0; i < 8; i++)
#pragma unroll
        for (int j = 0; j < 8; j++) acc[i][j] = 0.f;

    float4 a0, a1, b0, b1;

    auto store_tile = [&](int buf) {
        As[buf][acol + 0][arow]      = a0.x;
        As[buf][acol + 1][arow]      = a0.y;
        As[buf][acol + 2][arow]      = a0.z;
        As[buf][acol + 3][arow]      = a0.w;
        As[buf][acol + 0][arow + 64] = a1.x;
        As[buf][acol + 1][arow + 64] = a1.y;
        As[buf][acol + 2][arow + 64] = a1.z;
        As[buf][acol + 3][arow + 64] = a1.w;
        *(float4*)&Bs[buf][brow][bcol]     = b0;
        *(float4*)&Bs[buf][brow + 8][bcol] = b1;
    };

    auto compute = [&](int buf) {
#pragma unroll
        for (int k = 0; k < 16; k++) {
            float4 xa0 = *(const float4*)&As[buf][k][ty * 8];
            float4 xa1 = *(const float4*)&As[buf][k][ty * 8 + 4];
            float4 xb0 = *(const float4*)&Bs[buf][k][tx * 8];
            float4 xb1 = *(const float4*)&Bs[buf][k][tx * 8 + 4];
            float av[8] = {xa0.x, xa0.y, xa0.z, xa0.w, xa1.x, xa1.y, xa1.z, xa1.w};
            float bv[8] = {xb0.x, xb0.y, xb0.z, xb0.w, xb1.x, xb1.y, xb1.z, xb1.w};
#pragma unroll
            for (int i = 0; i < 8; i++)
#pragma unroll
                for (int j = 0; j < 8; j++)
                    acc[i][j] = fmaf(av[i], bv[j], acc[i][j]);
        }
    };

    // Prologue: tile 0
    a0 = *(const float4*)(Ap);
    a1 = *(const float4*)(Ap + AHalf);
    b0 = *(const float4*)(Bp);
    b1 = *(const float4*)(Bp + BHalf);
    store_tile(0);
    __syncthreads();

    const int nt = K >> 4;
    for (int t = 1; t < nt; t++) {
        Ap += 16;
        Bp += 16L * N;
        a0 = *(const float4*)(Ap);
        a1 = *(const float4*)(Ap + AHalf);
        b0 = *(const float4*)(Bp);
        b1 = *(const float4*)(Bp + BHalf);
        compute((t - 1) & 1);
        store_tile(t & 1);
        __syncthreads();
    }
    compute((nt - 1) & 1);

    float* Cp = C + (bm + ty * 8) * (long)N + bn + tx * 8;
#pragma unroll
    for (int i = 0; i < 8; i++) {
        *(float4*)(Cp + (long)i * N)     = make_float4(acc[i][0], acc[i][1], acc[i][2], acc[i][3]);
        *(float4*)(Cp + (long)i * N + 4) = make_float4(acc[i][4], acc[i][5], acc[i][6], acc[i][7]);
    }
}

// ---------------------------------------------------------------------------
// RoPE (NeoX-style, rotary_dim = head_dim), applied in-place to q and k
// sections of g_qkv. One thread per (row, head, freq-index) pair.
// ---------------------------------------------------------------------------
__global__ void rope_kernel(const int* __restrict__ pos) {
    const int TOT = BS_ROWS * (NQH + NKV) * 64;
    int idx = blockIdx.x * blockDim.x + threadIdx.x;
    if (idx >= TOT) return;
    int i   = idx & 63;
    int h   = (idx >> 6) % (NQH + NKV);
    int row = idx / (64 * (NQH + NKV));
    int p   = pos[row];

    long col = (long)h * HD;   // q heads 0..31 then k heads 32..39, contiguous
    float* ptr = g_qkv + (long)row * QKV_N + col;

    // inv_freq = 10000^(-i/64) = exp(-i * ln(10000)/64)
    float inv = expf(-(float)i * 0.14391156831212787f);
    float ang = (float)p * inv;
    float sn, cs;
    sincosf(ang, &sn, &cs);
    float x1 = ptr[i], x2 = ptr[i + 64];
    ptr[i]      = x1 * cs - x2 * sn;
    ptr[i + 64] = x2 * cs + x1 * sn;
}

// ---------------------------------------------------------------------------
// Flash attention (causal, GQA rep=4). One block per (q-tile of 64, head, b).
// Q,K stored transposed in smem ([d][row], conflict-free STS), V row-major.
// Online softmax with half-warp shuffle row reductions.
// ---------------------------------------------------------------------------
__global__ __launch_bounds__(256, 1)
void flash_attn() {
    extern __shared__ float sm[];
    float* QsT = sm;             // [128][64]
    float* KsT = sm + 8192;      // [128][64]
    float* Vs  = sm + 16384;     // [64][128]
    float* Ps  = sm + 24576;     // [64][64]

    const float* qkv = g_qkv;
    float* out = g_attn;

    const int tid = threadIdx.x;
    const int qt  = blockIdx.x;
    const int h   = blockIdx.y;
    const int b   = blockIdx.z;
    const int kvh = h >> 2;      // GQA: 4 q heads per kv head
    const int q0  = qt << 6;
    const int ty  = tid >> 4;    // 0..15 -> rows ty*4..ty*4+3
    const int tx  = tid & 15;    // 0..15

    // Load Q tile transposed: QsT[d][r]
    const float* gq = qkv + ((long)(b * SEQ + q0)) * QKV_N + h * HD;
#pragma unroll
    for (int e = tid; e < 2048; e += 256) {
        int c = e & 63;
        int d = (e >> 6) << 2;
        float4 v = *(const float4*)(gq + (long)c * QKV_N + d);
        QsT[(d + 0) * 64 + c] = v.x;
        QsT[(d + 1) * 64 + c] = v.y;
        QsT[(d + 2) * 64 + c] = v.z;
        QsT[(d + 3) * 64 + c] = v.w;
    }

    float m_prev[4], l_run[4], o[4][8];
#pragma unroll
    for (int i = 0; i < 4; i++) {
        m_prev[i] = -3.0e38f;
        l_run[i]  = 0.f;
#pragma unroll
        for (int j = 0; j < 8; j++) o[i][j] = 0.f;
    }

    const float scale = 0.08838834764831845f;   // 1/sqrt(128)

    for (int kt = 0; kt <= qt; kt++) {
        const int k0 = kt << 6;
        __syncthreads();   // prev iteration done with KsT/Vs/Ps; Q load visible

        // K tile transposed: KsT[d][c]
        const float* gk = qkv + ((long)(b * SEQ + k0)) * QKV_N + NQH * HD + kvh * HD;
#pragma unroll
        for (int e = tid; e < 2048; e += 256) {
            int c = e & 63;
            int d = (e >> 6) << 2;
            float4 v = *(const float4*)(gk + (long)c * QKV_N + d);
            KsT[(d + 0) * 64 + c] = v.x;
            KsT[(d + 1) * 64 + c] = v.y;
            KsT[(d + 2) * 64 + c] = v.z;
            KsT[(d + 3) * 64 + c] = v.w;
        }
        // V tile row-major: Vs[r][d]
        const float* gv = gk + NKV * HD;
#pragma unroll
        for (int e = tid; e < 2048; e += 256) {
            int r = e >> 5;
            int d = (e & 31) << 2;
            *(float4*)&Vs[r * 128 + d] = *(const float4*)(gv + (long)r * QKV_N + d);
        }
        __syncthreads();

        // S = Q K^T  (4x4 per thread), outer-product over d
        float acc[4][4];
#pragma unroll
        for (int i = 0; i < 4; i++)
#pragma unroll
            for (int j = 0; j < 4; j++) acc[i][j] = 0.f;

#pragma unroll 8
        for (int d = 0; d < 128; d++) {
            float4 q4 = *(const float4*)&QsT[d * 64 + (ty << 2)];
            float4 k4 = *(const float4*)&KsT[d * 64 + (tx << 2)];
            float qa[4] = {q4.x, q4.y, q4.z, q4.w};
            float ka[4] = {k4.x, k4.y, k4.z, k4.w};
#pragma unroll
            for (int i = 0; i < 4; i++)
#pragma unroll
                for (int j = 0; j < 4; j++)
                    acc[i][j] = fmaf(qa[i], ka[j], acc[i][j]);
        }

        // Scale, causal mask (only diagonal tile partial), online softmax.
        const bool diag = (kt == qt);
        float alpha[4];
#pragma unroll
        for (int i = 0; i < 4; i++) {
            const int qrow = q0 + (ty << 2) + i;
            float tmp[4];
#pragma unroll
            for (int j = 0; j < 4; j++) {
                float s = acc[i][j] * scale;
                if (diag && (k0 + (tx << 2) + j > qrow)) s = -1.0e30f;
                tmp[j] = s;
            }
            float rm = fmaxf(fmaxf(tmp[0], tmp[1]), fmaxf(tmp[2], tmp[3]));
            rm = fmaxf(rm, __shfl_xor_sync(0xffffffffu, rm, 1, 16));
            rm = fmaxf(rm, __shfl_xor_sync(0xffffffffu, rm, 2, 16));
            rm = fmaxf(rm, __shfl_xor_sync(0xffffffffu, rm, 4, 16));
            rm = fmaxf(rm, __shfl_xor_sync(0xffffffffu, rm, 8, 16));
            float m_new = fmaxf(m_prev[i], rm);
            float al = expf(m_prev[i] - m_new);
            float rs = 0.f;
#pragma unroll
            for (int j = 0; j < 4; j++) {
                float p = expf(tmp[j] - m_new);
                tmp[j] = p;
                rs += p;
            }
            rs += __shfl_xor_sync(0xffffffffu, rs, 1, 16);
            rs += __shfl_xor_sync(0xffffffffu, rs, 2, 16);
            rs += __shfl_xor_sync(0xffffffffu, rs, 4, 16);
            rs += __shfl_xor_sync(0xffffffffu, rs, 8, 16);
            l_run[i]  = l_run[i] * al + rs;
            m_prev[i] = m_new;
            alpha[i]  = al;
            *(float4*)&Ps[(((ty << 2) + i) << 6) + (tx << 2)] =
                make_float4(tmp[0], tmp[1], tmp[2], tmp[3]);
        }
        __syncthreads();

        // O = diag(alpha) O + P V   (thread map: rows ty*4.., cols tx*8..)
#pragma unroll
        for (int i = 0; i < 4; i++)
#pragma unroll
            for (int j = 0; j < 8; j++) o[i][j] *= alpha[i];

#pragma unroll 4
        for (int k = 0; k < 64; k++) {
            float pv[4];
#pragma unroll
            for (int i = 0; i < 4; i++) pv[i] = Ps[(((ty << 2) + i) << 6) + k];
            float4 v0 = *(const float4*)&Vs[k * 128 + (tx << 3)];
            float4 v1 = *(const float4*)&Vs[k * 128 + (tx << 3) + 4];
            float vv[8] = {v0.x, v0.y, v0.z, v0.w, v1.x, v1.y, v1.z, v1.w};
#pragma unroll
            for (int i = 0; i < 4; i++)
#pragma unroll
                for (int j = 0; j < 8; j++)
                    o[i][j] = fmaf(pv[i], vv[j], o[i][j]);
        }
    }

    // Normalize and write: out[b*S + q][h*128 + c]
#pragma unroll
    for (int i = 0; i < 4; i++) {
        float inv = 1.0f / l_run[i];
        long row = (long)(b * SEQ + q0 + (ty << 2) + i);
        float* po = out + row * HID + h * HD + (tx << 3);
        *(float4*)po       = make_float4(o[i][0] * inv, o[i][1] * inv, o[i][2] * inv, o[i][3] * inv);
        *(float4*)(po + 4) = make_float4(o[i][4] * inv, o[i][5] * inv, o[i][6] * inv, o[i][7] * inv);
    }
}

// Thin wrappers so the GEMM kernel can read/write the __device__ scratch
// without any host-side symbol-address lookup.
__global__ __launch_bounds__(256, 2)
void sgemm_qkv(const float* __restrict__ A, const float* __restrict__ Bm) {
    // forward into a plain device function would duplicate code; instead we
    // re-launch sgemm128 with global pointers from the host via the device
    // symbols below.
}

// ---------------------------------------------------------------------------
// Launch: QKV GEMM -> RoPE -> flash attention -> O GEMM
// ---------------------------------------------------------------------------
extern "C" void kernel_launch(void* const* d_in, const int* in_sizes, int n_in,
                              void* d_out, int out_size) {
    const int*   positions = (const int*)d_in[0];
    const float* hidden    = (const float*)d_in[1];
    const float* w_qkv     = (const float*)d_in[2];
    const float* w_o       = (const float*)d_in[3];
    float*       out       = (float*)d_out;

    // Resolve scratch addresses once per call via the runtime's static mapping.
    // cudaGetSymbolAddress is a pure lookup (no stream interaction) but we
    // avoid it anyway: take addresses through a device-linked constant trick
    // is not possible host-side, so use the one sanctioned API.
    static float* qkv  = nullptr;
    static float* attn = nullptr;
    if (!qkv) {
        cudaGetSymbolAddress((void**)&qkv, g_qkv);
        cudaGetSymbolAddress((void**)&attn, g_attn);
    }

    dim3 blk(256);

    dim3 g1(QKV_N / 128, BS_ROWS / 128);
    sgemm128<<<g1, blk>>>(hidden, w_qkv, qkv, BS_ROWS, QKV_N, HID);

    const int tot = BS_ROWS * (NQH + NKV) * 64;
    rope_kernel<<<(tot + 255) / 256, 256>>>(positions);

    static bool smem_set = false;
    if (!smem_set) {
        cudaFuncSetAttribute(flash_attn, cudaFuncAttributeMaxDynamicSharedMemorySize, 114688);
        smem_set = true;
    }
    dim3 gf(SEQ / 64, NQH, BATCH);
    flash_attn<<<gf, blk, 114688>>>();

    dim3 g2(HID / 128, BS_ROWS / 128);
    sgemm128<<<g2, blk>>>(attn, w_o, out, BS_ROWS, HID, HID);
}

// round 5
// speedup vs baseline: 1.3860x; 1.3860x over previous
#include <cuda_runtime.h>
#include <cuda_bf16.h>
#include <math.h>
#include <stdint.h>

// Problem constants
#define BATCH   4
#define SEQ     1024
#define HID     4096
#define NQH     32
#define NKV     8
#define HD      128
#define QKV_N   6144                 // (NH + 2*NKV) * HD
#define BS_ROWS 4096                 // BATCH * SEQ

// ---------------------------------------------------------------------------
// Scratch (__device__ globals; allocation-free rule)
// ---------------------------------------------------------------------------
__device__ float         g_qkv[(size_t)BS_ROWS * QKV_N];
__device__ __nv_bfloat16 g_hid_hi[(size_t)BS_ROWS * HID];
__device__ __nv_bfloat16 g_hid_lo[(size_t)BS_ROWS * HID];
__device__ __nv_bfloat16 g_wqkvT_hi[(size_t)QKV_N * HID];     // [N, K] (B^T)
__device__ __nv_bfloat16 g_wqkvT_lo[(size_t)QKV_N * HID];
__device__ __nv_bfloat16 g_woT_hi[(size_t)HID * HID];
__device__ __nv_bfloat16 g_woT_lo[(size_t)HID * HID];
__device__ __nv_bfloat16 g_attn_hi[(size_t)BS_ROWS * HID];
__device__ __nv_bfloat16 g_attn_lo[(size_t)BS_ROWS * HID];

__device__ __forceinline__ uint32_t smem_u32(const void* p) {
    uint32_t a;
    asm("{ .reg .u64 t; cvta.to.shared.u64 t, %1; cvt.u32.u64 %0, t; }" : "=r"(a) : "l"(p));
    return a;
}

// ---------------------------------------------------------------------------
// Split kernels: f32 -> (hi, lo) bf16
// ---------------------------------------------------------------------------
__global__ void split_act(const float* __restrict__ in,
                          __nv_bfloat16* __restrict__ hi,
                          __nv_bfloat16* __restrict__ lo, int n4) {
    int i = blockIdx.x * blockDim.x + threadIdx.x;
    if (i >= n4) return;
    float4 v = ((const float4*)in)[i];
    float x[4] = {v.x, v.y, v.z, v.w};
#pragma unroll
    for (int j = 0; j < 4; j++) {
        __nv_bfloat16 h = __float2bfloat16(x[j]);
        hi[i * 4 + j] = h;
        lo[i * 4 + j] = __float2bfloat16(x[j] - __bfloat162float(h));
    }
}

// W[Kdim, Ndim] f32 -> transposed hi/lo [Ndim, Kdim] bf16 (tiled 32x32)
__global__ void split_T(const float* __restrict__ W,
                        __nv_bfloat16* __restrict__ hiT,
                        __nv_bfloat16* __restrict__ loT, int Kdim, int Ndim) {
    __shared__ float t[32][33];
    int n0 = blockIdx.x * 32, k0 = blockIdx.y * 32;
    t[threadIdx.y][threadIdx.x] = W[(long)(k0 + threadIdx.y) * Ndim + n0 + threadIdx.x];
    __syncthreads();
    float x = t[threadIdx.x][threadIdx.y];
    long o = (long)(n0 + threadIdx.y) * Kdim + k0 + threadIdx.x;
    __nv_bfloat16 h = __float2bfloat16(x);
    hiT[o] = h;
    loT[o] = __float2bfloat16(x - __bfloat162float(h));
}

// ---------------------------------------------------------------------------
// HMMA GEMM: C[M,N] = A[M,K] @ Bt[N,K]^T, hi/lo 3-pass bf16 mma.sync.
// CTA 128x128, BK=32, 8 warps (2Mx4N), warp tile 64x32.
// Smem tiles stored as contiguous 8x8-bf16 matrices (128B each) -> conflict-free
// ldmatrix. cp.async double-buffered.
// ---------------------------------------------------------------------------
#define STAGE_BYTES 32768
#define A_HI_OFF 0
#define A_LO_OFF 8192
#define B_HI_OFF 16384
#define B_LO_OFF 24576
// matrix (rm, km) of a 128x32 operand block lives at (rm*4+km)*128

#define LDSM4(R, ADDR) \
    asm volatile("ldmatrix.sync.aligned.m8n8.x4.shared.b16 {%0,%1,%2,%3}, [%4];" \
                 : "=r"((R)[0]), "=r"((R)[1]), "=r"((R)[2]), "=r"((R)[3]) : "r"(ADDR))

#define MMA_BF16(ACC, A, B) \
    asm volatile("mma.sync.aligned.m16n8k16.row.col.f32.bf16.bf16.f32 " \
                 "{%0,%1,%2,%3}, {%4,%5,%6,%7}, {%8,%9}, {%0,%1,%2,%3};" \
                 : "+f"((ACC)[0]), "+f"((ACC)[1]), "+f"((ACC)[2]), "+f"((ACC)[3]) \
                 : "r"((A)[0]), "r"((A)[1]), "r"((A)[2]), "r"((A)[3]), \
                   "r"((B)[0]), "r"((B)[1]))

__device__ __forceinline__ void cp16(uint32_t dst, const void* src) {
    asm volatile("cp.async.cg.shared.global [%0], [%1], 16;" :: "r"(dst), "l"(src));
}

__device__ __forceinline__ void g2s_tile(
    uint32_t sb,
    const __nv_bfloat16* __restrict__ Ahi, const __nv_bfloat16* __restrict__ Alo,
    const __nv_bfloat16* __restrict__ Bhi, const __nv_bfloat16* __restrict__ Blo,
    long bm, long bn, int k0, int K, int tid)
{
#pragma unroll
    for (int i = 0; i < 2; i++) {
        int e  = tid + i * 256;        // 0..511
        int r  = e >> 2;               // 0..127
        int kc = e & 3;                // 16B chunk within BK=32
        uint32_t moff = (uint32_t)((((r >> 3) << 2) + kc) * 128 + (r & 7) * 16);
        long ga = (bm + r) * (long)K + k0 + kc * 8;
        long gb = (bn + r) * (long)K + k0 + kc * 8;
        cp16(sb + A_HI_OFF + moff, Ahi + ga);
        cp16(sb + A_LO_OFF + moff, Alo + ga);
        cp16(sb + B_HI_OFF + moff, Bhi + gb);
        cp16(sb + B_LO_OFF + moff, Blo + gb);
    }
}

__global__ __launch_bounds__(256, 1)
void gemm_mma3(const __nv_bfloat16* __restrict__ Ahi, const __nv_bfloat16* __restrict__ Alo,
               const __nv_bfloat16* __restrict__ Bhi, const __nv_bfloat16* __restrict__ Blo,
               float* __restrict__ C, int N, int K)
{
    extern __shared__ char smx[];
    const uint32_t s0 = smem_u32(smx);
    const int tid  = threadIdx.x;
    const int wid  = tid >> 5;
    const int lane = tid & 31;
    const int wm   = wid >> 2;        // 0..1  (M)
    const int wn   = wid & 3;         // 0..3  (N)
    const int sel  = lane >> 3;       // ldmatrix lane group
    const int rowin = lane & 7;
    const int g    = lane >> 2;       // mma row group
    const int tq   = lane & 3;        // mma quad thread
    const long bm = (long)blockIdx.y * 128;
    const long bn = (long)blockIdx.x * 128;

    float acc[4][4][4];
#pragma unroll
    for (int i = 0; i < 4; i++)
#pragma unroll
        for (int j = 0; j < 4; j++)
#pragma unroll
            for (int k = 0; k < 4; k++) acc[i][j][k] = 0.f;

    const int NT = K >> 5;
    g2s_tile(s0, Ahi, Alo, Bhi, Blo, bm, bn, 0, K, tid);
    asm volatile("cp.async.commit_group;" ::: "memory");

    for (int t = 0; t < NT; t++) {
        if (t + 1 < NT) {
            g2s_tile(s0 + ((t + 1) & 1) * STAGE_BYTES,
                     Ahi, Alo, Bhi, Blo, bm, bn, (t + 1) << 5, K, tid);
            asm volatile("cp.async.commit_group;" ::: "memory");
            asm volatile("cp.async.wait_group 1;" ::: "memory");
        } else {
            asm volatile("cp.async.wait_group 0;" ::: "memory");
        }
        __syncthreads();

        const uint32_t sb = s0 + (t & 1) * STAGE_BYTES;
#pragma unroll
        for (int ks = 0; ks < 2; ks++) {
            uint32_t ah[4][4], al[4][4], bh[4][2], bl[4][2];
#pragma unroll
            for (int mt = 0; mt < 4; mt++) {
                int rm = wm * 8 + 2 * mt + (sel & 1);
                int km = 2 * ks + (sel >> 1);
                uint32_t off = (uint32_t)(((rm << 2) + km) * 128 + rowin * 16);
                LDSM4(ah[mt], sb + A_HI_OFF + off);
                LDSM4(al[mt], sb + A_LO_OFF + off);
            }
#pragma unroll
            for (int bt = 0; bt < 2; bt++) {
                int nm = wn * 4 + 2 * bt + (sel >> 1);
                int km = 2 * ks + (sel & 1);
                uint32_t off = (uint32_t)(((nm << 2) + km) * 128 + rowin * 16);
                uint32_t r4[4];
                LDSM4(r4, sb + B_HI_OFF + off);
                bh[2 * bt][0] = r4[0]; bh[2 * bt][1] = r4[1];
                bh[2 * bt + 1][0] = r4[2]; bh[2 * bt + 1][1] = r4[3];
                LDSM4(r4, sb + B_LO_OFF + off);
                bl[2 * bt][0] = r4[0]; bl[2 * bt][1] = r4[1];
                bl[2 * bt + 1][0] = r4[2]; bl[2 * bt + 1][1] = r4[3];
            }
#pragma unroll
            for (int mt = 0; mt < 4; mt++)
#pragma unroll
                for (int nt = 0; nt < 4; nt++) {
                    MMA_BF16(acc[mt][nt], ah[mt], bh[nt]);
                    MMA_BF16(acc[mt][nt], ah[mt], bl[nt]);
                    MMA_BF16(acc[mt][nt], al[mt], bh[nt]);
                }
        }
        __syncthreads();
    }

    // Epilogue: direct global stores (float2 per 4-lane quad-row)
#pragma unroll
    for (int mt = 0; mt < 4; mt++) {
        long row0 = bm + wm * 64 + mt * 16 + g;
#pragma unroll
        for (int nt = 0; nt < 4; nt++) {
            long col = bn + wn * 32 + nt * 8 + tq * 2;
            *(float2*)&C[row0 * N + col]       = make_float2(acc[mt][nt][0], acc[mt][nt][1]);
            *(float2*)&C[(row0 + 8) * N + col] = make_float2(acc[mt][nt][2], acc[mt][nt][3]);
        }
    }
}

// ---------------------------------------------------------------------------
// RoPE (NeoX, full head_dim) in-place on q|k of g_qkv
// ---------------------------------------------------------------------------
__global__ void rope_kernel(const int* __restrict__ pos) {
    const int TOT = BS_ROWS * (NQH + NKV) * 64;
    int idx = blockIdx.x * blockDim.x + threadIdx.x;
    if (idx >= TOT) return;
    int i   = idx & 63;
    int h   = (idx >> 6) % (NQH + NKV);
    int row = idx / (64 * (NQH + NKV));
    int p   = pos[row];

    float* ptr = g_qkv + (long)row * QKV_N + (long)h * HD;
    float inv = expf(-(float)i * 0.14391156831212787f);   // ln(10000)/64
    float ang = (float)p * inv;
    float sn, cs;
    sincosf(ang, &sn, &cs);
    float x1 = ptr[i], x2 = ptr[i + 64];
    ptr[i]      = x1 * cs - x2 * sn;
    ptr[i + 64] = x2 * cs + x1 * sn;
}

// ---------------------------------------------------------------------------
// Flash attention (fp32, causal, GQA rep=4); emits hi/lo bf16 for GEMM2.
// ---------------------------------------------------------------------------
__global__ __launch_bounds__(256, 1)
void flash_attn() {
    extern __shared__ float smf[];
    float* QsT = smf;             // [128][64]
    float* KsT = smf + 8192;      // [128][64]
    float* Vs  = smf + 16384;     // [64][128]
    float* Ps  = smf + 24576;     // [64][64]

    const float* qkv = g_qkv;
    const int tid = threadIdx.x;
    const int qt  = blockIdx.x;
    const int h   = blockIdx.y;
    const int b   = blockIdx.z;
    const int kvh = h >> 2;
    const int q0  = qt << 6;
    const int ty  = tid >> 4;
    const int tx  = tid & 15;

    const float* gq = qkv + ((long)(b * SEQ + q0)) * QKV_N + h * HD;
#pragma unroll
    for (int e = tid; e < 2048; e += 256) {
        int c = e & 63;
        int d = (e >> 6) << 2;
        float4 v = *(const float4*)(gq + (long)c * QKV_N + d);
        QsT[(d + 0) * 64 + c] = v.x;
        QsT[(d + 1) * 64 + c] = v.y;
        QsT[(d + 2) * 64 + c] = v.z;
        QsT[(d + 3) * 64 + c] = v.w;
    }

    float m_prev[4], l_run[4], o[4][8];
#pragma unroll
    for (int i = 0; i < 4; i++) {
        m_prev[i] = -3.0e38f;
        l_run[i]  = 0.f;
#pragma unroll
        for (int j = 0; j < 8; j++) o[i][j] = 0.f;
    }

    const float scale = 0.08838834764831845f;

    for (int kt = 0; kt <= qt; kt++) {
        const int k0 = kt << 6;
        __syncthreads();

        const float* gk = qkv + ((long)(b * SEQ + k0)) * QKV_N + NQH * HD + kvh * HD;
#pragma unroll
        for (int e = tid; e < 2048; e += 256) {
            int c = e & 63;
            int d = (e >> 6) << 2;
            float4 v = *(const float4*)(gk + (long)c * QKV_N + d);
            KsT[(d + 0) * 64 + c] = v.x;
            KsT[(d + 1) * 64 + c] = v.y;
            KsT[(d + 2) * 64 + c] = v.z;
            KsT[(d + 3) * 64 + c] = v.w;
        }
        const float* gv = gk + NKV * HD;
#pragma unroll
        for (int e = tid; e < 2048; e += 256) {
            int r = e >> 5;
            int d = (e & 31) << 2;
            *(float4*)&Vs[r * 128 + d] = *(const float4*)(gv + (long)r * QKV_N + d);
        }
        __syncthreads();

        float acc[4][4];
#pragma unroll
        for (int i = 0; i < 4; i++)
#pragma unroll
            for (int j = 0; j < 4; j++) acc[i][j] = 0.f;

#pragma unroll 8
        for (int d = 0; d < 128; d++) {
            float4 q4 = *(const float4*)&QsT[d * 64 + (ty << 2)];
            float4 k4 = *(const float4*)&KsT[d * 64 + (tx << 2)];
            float qa[4] = {q4.x, q4.y, q4.z, q4.w};
            float ka[4] = {k4.x, k4.y, k4.z, k4.w};
#pragma unroll
            for (int i = 0; i < 4; i++)
#pragma unroll
                for (int j = 0; j < 4; j++)
                    acc[i][j] = fmaf(qa[i], ka[j], acc[i][j]);
        }

        const bool diag = (kt == qt);
        float alpha[4];
#pragma unroll
        for (int i = 0; i < 4; i++) {
            const int qrow = q0 + (ty << 2) + i;
            float tmp[4];
#pragma unroll
            for (int j = 0; j < 4; j++) {
                float s = acc[i][j] * scale;
                if (diag && (k0 + (tx << 2) + j > qrow)) s = -1.0e30f;
                tmp[j] = s;
            }
            float rm = fmaxf(fmaxf(tmp[0], tmp[1]), fmaxf(tmp[2], tmp[3]));
            rm = fmaxf(rm, __shfl_xor_sync(0xffffffffu, rm, 1, 16));
            rm = fmaxf(rm, __shfl_xor_sync(0xffffffffu, rm, 2, 16));
            rm = fmaxf(rm, __shfl_xor_sync(0xffffffffu, rm, 4, 16));
            rm = fmaxf(rm, __shfl_xor_sync(0xffffffffu, rm, 8, 16));
            float m_new = fmaxf(m_prev[i], rm);
            float al = expf(m_prev[i] - m_new);
            float rs = 0.f;
#pragma unroll
            for (int j = 0; j < 4; j++) {
                float p = expf(tmp[j] - m_new);
                tmp[j] = p;
                rs += p;
            }
            rs += __shfl_xor_sync(0xffffffffu, rs, 1, 16);
            rs += __shfl_xor_sync(0xffffffffu, rs, 2, 16);
            rs += __shfl_xor_sync(0xffffffffu, rs, 4, 16);
            rs += __shfl_xor_sync(0xffffffffu, rs, 8, 16);
            l_run[i]  = l_run[i] * al + rs;
            m_prev[i] = m_new;
            alpha[i]  = al;
            *(float4*)&Ps[(((ty << 2) + i) << 6) + (tx << 2)] =
                make_float4(tmp[0], tmp[1], tmp[2], tmp[3]);
        }
        __syncthreads();

#pragma unroll
        for (int i = 0; i < 4; i++)
#pragma unroll
            for (int j = 0; j < 8; j++) o[i][j] *= alpha[i];

#pragma unroll 4
        for (int k = 0; k < 64; k++) {
            float pv[4];
#pragma unroll
            for (int i = 0; i < 4; i++) pv[i] = Ps[(((ty << 2) + i) << 6) + k];
            float4 v0 = *(const float4*)&Vs[k * 128 + (tx << 3)];
            float4 v1 = *(const float4*)&Vs[k * 128 + (tx << 3) + 4];
            float vv[8] = {v0.x, v0.y, v0.z, v0.w, v1.x, v1.y, v1.z, v1.w};
#pragma unroll
            for (int i = 0; i < 4; i++)
#pragma unroll
                for (int j = 0; j < 8; j++)
                    o[i][j] = fmaf(pv[i], vv[j], o[i][j]);
        }
    }

    // Normalize; write hi/lo bf16 (GEMM2 operand A)
#pragma unroll
    for (int i = 0; i < 4; i++) {
        float inv = 1.0f / l_run[i];
        long row = (long)(b * SEQ + q0 + (ty << 2) + i);
        long off = row * HID + h * HD + (tx << 3);
#pragma unroll
        for (int j = 0; j < 8; j++) {
            float v = o[i][j] * inv;
            __nv_bfloat16 hb = __float2bfloat16(v);
            g_attn_hi[off + j] = hb;
            g_attn_lo[off + j] = __float2bfloat16(v - __bfloat162float(hb));
        }
    }
}

// ---------------------------------------------------------------------------
// Launch: splits -> QKV HMMA-GEMM -> RoPE -> flash -> O HMMA-GEMM
// ---------------------------------------------------------------------------
extern "C" void kernel_launch(void* const* d_in, const int* in_sizes, int n_in,
                              void* d_out, int out_size) {
    const int*   positions = (const int*)d_in[0];
    const float* hidden    = (const float*)d_in[1];
    const float* w_qkv     = (const float*)d_in[2];
    const float* w_o       = (const float*)d_in[3];
    float*       out       = (float*)d_out;

    static __nv_bfloat16 *hid_hi, *hid_lo, *wqT_hi, *wqT_lo, *woT_hi, *woT_lo;
    static __nv_bfloat16 *attn_hi, *attn_lo;
    static float* qkv;
    static bool init = false;
    if (!init) {
        cudaGetSymbolAddress((void**)&hid_hi,  g_hid_hi);
        cudaGetSymbolAddress((void**)&hid_lo,  g_hid_lo);
        cudaGetSymbolAddress((void**)&wqT_hi,  g_wqkvT_hi);
        cudaGetSymbolAddress((void**)&wqT_lo,  g_wqkvT_lo);
        cudaGetSymbolAddress((void**)&woT_hi,  g_woT_hi);
        cudaGetSymbolAddress((void**)&woT_lo,  g_woT_lo);
        cudaGetSymbolAddress((void**)&attn_hi, g_attn_hi);
        cudaGetSymbolAddress((void**)&attn_lo, g_attn_lo);
        cudaGetSymbolAddress((void**)&qkv,     g_qkv);
        cudaFuncSetAttribute(gemm_mma3, cudaFuncAttributeMaxDynamicSharedMemorySize,
                             2 * STAGE_BYTES);
        cudaFuncSetAttribute(flash_attn, cudaFuncAttributeMaxDynamicSharedMemorySize, 114688);
        init = true;
    }

    // Split inputs to bf16 hi/lo (weights transposed to [N, K])
    {
        int n4 = BS_ROWS * HID / 4;
        split_act<<<(n4 + 255) / 256, 256>>>(hidden, hid_hi, hid_lo, n4);
    }
    split_T<<<dim3(QKV_N / 32, HID / 32), dim3(32, 32)>>>(w_qkv, wqT_hi, wqT_lo, HID, QKV_N);
    split_T<<<dim3(HID / 32, HID / 32), dim3(32, 32)>>>(w_o, woT_hi, woT_lo, HID, HID);

    // QKV projection: [4096,4096] @ [4096,6144] -> g_qkv (f32)
    gemm_mma3<<<dim3(QKV_N / 128, BS_ROWS / 128), 256, 2 * STAGE_BYTES>>>(
        hid_hi, hid_lo, wqT_hi, wqT_lo, qkv, QKV_N, HID);

    const int tot = BS_ROWS * (NQH + NKV) * 64;
    rope_kernel<<<(tot + 255) / 256, 256>>>(positions);

    flash_attn<<<dim3(SEQ / 64, NQH, BATCH), 256, 114688>>>();

    // Output projection: [4096,4096] @ [4096,4096] -> out
    gemm_mma3<<<dim3(HID / 128, BS_ROWS / 128), 256, 2 * STAGE_BYTES>>>(
        attn_hi, attn_lo, woT_hi, woT_lo, out, HID, HID);
}

// round 6
// speedup vs baseline: 1.4351x; 1.0354x over previous
#include <cuda_runtime.h>
#include <cuda_bf16.h>
#include <math.h>
#include <stdint.h>

// Problem constants
#define BATCH   4
#define SEQ     1024
#define HID     4096
#define NQH     32
#define NKV     8
#define HD      128
#define QKV_N   6144                 // (NH + 2*NKV) * HD
#define BS_ROWS 4096                 // BATCH * SEQ

// ---------------------------------------------------------------------------
// Scratch (__device__ globals; allocation-free rule)
// ---------------------------------------------------------------------------
__device__ float         g_qkv[(size_t)BS_ROWS * QKV_N];
__device__ __nv_bfloat16 g_hid_hi[(size_t)BS_ROWS * HID];
__device__ __nv_bfloat16 g_hid_lo[(size_t)BS_ROWS * HID];
__device__ __nv_bfloat16 g_wqkvT_hi[(size_t)QKV_N * HID];     // [N, K] (B^T)
__device__ __nv_bfloat16 g_wqkvT_lo[(size_t)QKV_N * HID];
__device__ __nv_bfloat16 g_woT_hi[(size_t)HID * HID];
__device__ __nv_bfloat16 g_woT_lo[(size_t)HID * HID];
__device__ __nv_bfloat16 g_attn_hi[(size_t)BS_ROWS * HID];
__device__ __nv_bfloat16 g_attn_lo[(size_t)BS_ROWS * HID];

__device__ __forceinline__ uint32_t smem_u32(const void* p) {
    uint32_t a;
    asm("{ .reg .u64 t; cvta.to.shared.u64 t, %1; cvt.u32.u64 %0, t; }" : "=r"(a) : "l"(p));
    return a;
}

// ---------------------------------------------------------------------------
// Split kernels: f32 -> (hi, lo) bf16
// ---------------------------------------------------------------------------
__global__ void split_act(const float* __restrict__ in,
                          __nv_bfloat16* __restrict__ hi,
                          __nv_bfloat16* __restrict__ lo, int n4) {
    int i = blockIdx.x * blockDim.x + threadIdx.x;
    if (i >= n4) return;
    float4 v = ((const float4*)in)[i];
    float x[4] = {v.x, v.y, v.z, v.w};
#pragma unroll
    for (int j = 0; j < 4; j++) {
        __nv_bfloat16 h = __float2bfloat16(x[j]);
        hi[i * 4 + j] = h;
        lo[i * 4 + j] = __float2bfloat16(x[j] - __bfloat162float(h));
    }
}

// W[Kdim, Ndim] f32 -> transposed hi/lo [Ndim, Kdim] bf16 (tiled 32x32)
__global__ void split_T(const float* __restrict__ W,
                        __nv_bfloat16* __restrict__ hiT,
                        __nv_bfloat16* __restrict__ loT, int Kdim, int Ndim) {
    __shared__ float t[32][33];
    int n0 = blockIdx.x * 32, k0 = blockIdx.y * 32;
    t[threadIdx.y][threadIdx.x] = W[(long)(k0 + threadIdx.y) * Ndim + n0 + threadIdx.x];
    __syncthreads();
    float x = t[threadIdx.x][threadIdx.y];
    long o = (long)(n0 + threadIdx.y) * Kdim + k0 + threadIdx.x;
    __nv_bfloat16 h = __float2bfloat16(x);
    hiT[o] = h;
    loT[o] = __float2bfloat16(x - __bfloat162float(h));
}

// ---------------------------------------------------------------------------
// HMMA GEMM: C[M,N] = A[M,K] @ Bt[N,K]^T, hi/lo 3-pass bf16 mma.sync.
// CTA 128x128, BK=32, 512 threads = 16 warps (4Mx4N), warp tile 32x32.
// Smem: contiguous 8x8-bf16 matrices (128B), 3-stage cp.async ring,
// ONE __syncthreads per K-tile (lookahead-2 protects buffer reuse).
// ---------------------------------------------------------------------------
#define STAGE_BYTES 32768
#define NSTAGE 3
#define A_HI_OFF 0
#define A_LO_OFF 8192
#define B_HI_OFF 16384
#define B_LO_OFF 24576
// matrix (rm, km) of a 128x32 operand block lives at (rm*4+km)*128

#define LDSM4(R, ADDR) \
    asm volatile("ldmatrix.sync.aligned.m8n8.x4.shared.b16 {%0,%1,%2,%3}, [%4];" \
                 : "=r"((R)[0]), "=r"((R)[1]), "=r"((R)[2]), "=r"((R)[3]) : "r"(ADDR))

#define MMA_BF16(ACC, A, B) \
    asm volatile("mma.sync.aligned.m16n8k16.row.col.f32.bf16.bf16.f32 " \
                 "{%0,%1,%2,%3}, {%4,%5,%6,%7}, {%8,%9}, {%0,%1,%2,%3};" \
                 : "+f"((ACC)[0]), "+f"((ACC)[1]), "+f"((ACC)[2]), "+f"((ACC)[3]) \
                 : "r"((A)[0]), "r"((A)[1]), "r"((A)[2]), "r"((A)[3]), \
                   "r"((B)[0]), "r"((B)[1]))

__device__ __forceinline__ void cp16(uint32_t dst, const void* src) {
    asm volatile("cp.async.cg.shared.global [%0], [%1], 16;" :: "r"(dst), "l"(src));
}

__device__ __forceinline__ void g2s_tile(
    uint32_t sb,
    const __nv_bfloat16* __restrict__ Ahi, const __nv_bfloat16* __restrict__ Alo,
    const __nv_bfloat16* __restrict__ Bhi, const __nv_bfloat16* __restrict__ Blo,
    long bm, long bn, int k0, int K, int tid)
{
    // 512 threads: each does one 16B chunk per tensor
    int r  = tid >> 2;               // 0..127
    int kc = tid & 3;                // 16B chunk within BK=32
    uint32_t moff = (uint32_t)((((r >> 3) << 2) + kc) * 128 + (r & 7) * 16);
    long ga = (bm + r) * (long)K + k0 + kc * 8;
    long gb = (bn + r) * (long)K + k0 + kc * 8;
    cp16(sb + A_HI_OFF + moff, Ahi + ga);
    cp16(sb + A_LO_OFF + moff, Alo + ga);
    cp16(sb + B_HI_OFF + moff, Bhi + gb);
    cp16(sb + B_LO_OFF + moff, Blo + gb);
}

__global__ __launch_bounds__(512, 1)
void gemm_mma3(const __nv_bfloat16* __restrict__ Ahi, const __nv_bfloat16* __restrict__ Alo,
               const __nv_bfloat16* __restrict__ Bhi, const __nv_bfloat16* __restrict__ Blo,
               float* __restrict__ C, int N, int K)
{
    extern __shared__ char smx[];
    const uint32_t s0 = smem_u32(smx);
    const int tid  = threadIdx.x;
    const int wid  = tid >> 5;
    const int lane = tid & 31;
    const int wm   = wid >> 2;        // 0..3  (M)
    const int wn   = wid & 3;         // 0..3  (N)
    const int sel  = lane >> 3;       // ldmatrix lane group
    const int rowin = lane & 7;
    const int g    = lane >> 2;       // mma row group
    const int tq   = lane & 3;        // mma quad thread
    const long bm = (long)blockIdx.y * 128;
    const long bn = (long)blockIdx.x * 128;

    float acc[2][4][4];
#pragma unroll
    for (int i = 0; i < 2; i++)
#pragma unroll
        for (int j = 0; j < 4; j++)
#pragma unroll
            for (int k = 0; k < 4; k++) acc[i][j][k] = 0.f;

    const int NT = K >> 5;

    // Prologue: prefetch tiles 0 and 1
    g2s_tile(s0, Ahi, Alo, Bhi, Blo, bm, bn, 0, K, tid);
    asm volatile("cp.async.commit_group;" ::: "memory");
    g2s_tile(s0 + STAGE_BYTES, Ahi, Alo, Bhi, Blo, bm, bn, 32, K, tid);
    asm volatile("cp.async.commit_group;" ::: "memory");

    int stage = 0;            // buffer index of tile t
    int nstage = 2;           // buffer index of tile t+2 (== (stage+2)%3)
    for (int t = 0; t < NT; t++) {
        if (t == NT - 1) {
            asm volatile("cp.async.wait_group 0;" ::: "memory");
        } else {
            asm volatile("cp.async.wait_group 1;" ::: "memory");
        }
        __syncthreads();      // tile t ready; all warps done with buffer (t+2)%3

        if (t + 2 < NT) {
            g2s_tile(s0 + nstage * STAGE_BYTES,
                     Ahi, Alo, Bhi, Blo, bm, bn, (t + 2) << 5, K, tid);
            asm volatile("cp.async.commit_group;" ::: "memory");
        }

        const uint32_t sb = s0 + stage * STAGE_BYTES;
#pragma unroll
        for (int ks = 0; ks < 2; ks++) {
            uint32_t ah[2][4], al[2][4], bh[4][2], bl[4][2];
#pragma unroll
            for (int mt = 0; mt < 2; mt++) {
                int rm = wm * 4 + 2 * mt + (sel & 1);
                int km = 2 * ks + (sel >> 1);
                uint32_t off = (uint32_t)(((rm << 2) + km) * 128 + rowin * 16);
                LDSM4(ah[mt], sb + A_HI_OFF + off);
                LDSM4(al[mt], sb + A_LO_OFF + off);
            }
#pragma unroll
            for (int bt = 0; bt < 2; bt++) {
                int nm = wn * 4 + 2 * bt + (sel >> 1);
                int km = 2 * ks + (sel & 1);
                uint32_t off = (uint32_t)(((nm << 2) + km) * 128 + rowin * 16);
                uint32_t r4[4];
                LDSM4(r4, sb + B_HI_OFF + off);
                bh[2 * bt][0] = r4[0]; bh[2 * bt][1] = r4[1];
                bh[2 * bt + 1][0] = r4[2]; bh[2 * bt + 1][1] = r4[3];
                LDSM4(r4, sb + B_LO_OFF + off);
                bl[2 * bt][0] = r4[0]; bl[2 * bt][1] = r4[1];
                bl[2 * bt + 1][0] = r4[2]; bl[2 * bt + 1][1] = r4[3];
            }
#pragma unroll
            for (int mt = 0; mt < 2; mt++)
#pragma unroll
                for (int nt = 0; nt < 4; nt++) {
                    MMA_BF16(acc[mt][nt], ah[mt], bh[nt]);
                    MMA_BF16(acc[mt][nt], ah[mt], bl[nt]);
                    MMA_BF16(acc[mt][nt], al[mt], bh[nt]);
                }
        }
        stage  = (stage == NSTAGE - 1) ? 0 : stage + 1;
        nstage = (nstage == NSTAGE - 1) ? 0 : nstage + 1;
    }

    // Epilogue: direct global stores (float2 per 4-lane quad-row)
#pragma unroll
    for (int mt = 0; mt < 2; mt++) {
        long row0 = bm + wm * 32 + mt * 16 + g;
#pragma unroll
        for (int nt = 0; nt < 4; nt++) {
            long col = bn + wn * 32 + nt * 8 + tq * 2;
            *(float2*)&C[row0 * N + col]       = make_float2(acc[mt][nt][0], acc[mt][nt][1]);
            *(float2*)&C[(row0 + 8) * N + col] = make_float2(acc[mt][nt][2], acc[mt][nt][3]);
        }
    }
}

// ---------------------------------------------------------------------------
// RoPE (NeoX, full head_dim) in-place on q|k of g_qkv
// ---------------------------------------------------------------------------
__global__ void rope_kernel(const int* __restrict__ pos) {
    const int TOT = BS_ROWS * (NQH + NKV) * 64;
    int idx = blockIdx.x * blockDim.x + threadIdx.x;
    if (idx >= TOT) return;
    int i   = idx & 63;
    int h   = (idx >> 6) % (NQH + NKV);
    int row = idx / (64 * (NQH + NKV));
    int p   = pos[row];

    float* ptr = g_qkv + (long)row * QKV_N + (long)h * HD;
    float inv = expf(-(float)i * 0.14391156831212787f);   // ln(10000)/64
    float ang = (float)p * inv;
    float sn, cs;
    sincosf(ang, &sn, &cs);
    float x1 = ptr[i], x2 = ptr[i + 64];
    ptr[i]      = x1 * cs - x2 * sn;
    ptr[i + 64] = x2 * cs + x1 * sn;
}

// ---------------------------------------------------------------------------
// Flash attention (fp32, causal, GQA rep=4); emits hi/lo bf16 for GEMM2.
// ---------------------------------------------------------------------------
__global__ __launch_bounds__(256, 1)
void flash_attn() {
    extern __shared__ float smf[];
    float* QsT = smf;             // [128][64]
    float* KsT = smf + 8192;      // [128][64]
    float* Vs  = smf + 16384;     // [64][128]
    float* Ps  = smf + 24576;     // [64][64]

    const float* qkv = g_qkv;
    const int tid = threadIdx.x;
    const int qt  = blockIdx.x;
    const int h   = blockIdx.y;
    const int b   = blockIdx.z;
    const int kvh = h >> 2;
    const int q0  = qt << 6;
    const int ty  = tid >> 4;
    const int tx  = tid & 15;

    const float* gq = qkv + ((long)(b * SEQ + q0)) * QKV_N + h * HD;
#pragma unroll
    for (int e = tid; e < 2048; e += 256) {
        int c = e & 63;
        int d = (e >> 6) << 2;
        float4 v = *(const float4*)(gq + (long)c * QKV_N + d);
        QsT[(d + 0) * 64 + c] = v.x;
        QsT[(d + 1) * 64 + c] = v.y;
        QsT[(d + 2) * 64 + c] = v.z;
        QsT[(d + 3) * 64 + c] = v.w;
    }

    float m_prev[4], l_run[4], o[4][8];
#pragma unroll
    for (int i = 0; i < 4; i++) {
        m_prev[i] = -3.0e38f;
        l_run[i]  = 0.f;
#pragma unroll
        for (int j = 0; j < 8; j++) o[i][j] = 0.f;
    }

    const float scale = 0.08838834764831845f;

    for (int kt = 0; kt <= qt; kt++) {
        const int k0 = kt << 6;
        __syncthreads();

        const float* gk = qkv + ((long)(b * SEQ + k0)) * QKV_N + NQH * HD + kvh * HD;
#pragma unroll
        for (int e = tid; e < 2048; e += 256) {
            int c = e & 63;
            int d = (e >> 6) << 2;
            float4 v = *(const float4*)(gk + (long)c * QKV_N + d);
            KsT[(d + 0) * 64 + c] = v.x;
            KsT[(d + 1) * 64 + c] = v.y;
            KsT[(d + 2) * 64 + c] = v.z;
            KsT[(d + 3) * 64 + c] = v.w;
        }
        const float* gv = gk + NKV * HD;
#pragma unroll
        for (int e = tid; e < 2048; e += 256) {
            int r = e >> 5;
            int d = (e & 31) << 2;
            *(float4*)&Vs[r * 128 + d] = *(const float4*)(gv + (long)r * QKV_N + d);
        }
        __syncthreads();

        float acc[4][4];
#pragma unroll
        for (int i = 0; i < 4; i++)
#pragma unroll
            for (int j = 0; j < 4; j++) acc[i][j] = 0.f;

#pragma unroll 8
        for (int d = 0; d < 128; d++) {
            float4 q4 = *(const float4*)&QsT[d * 64 + (ty << 2)];
            float4 k4 = *(const float4*)&KsT[d * 64 + (tx << 2)];
            float qa[4] = {q4.x, q4.y, q4.z, q4.w};
            float ka[4] = {k4.x, k4.y, k4.z, k4.w};
#pragma unroll
            for (int i = 0; i < 4; i++)
#pragma unroll
                for (int j = 0; j < 4; j++)
                    acc[i][j] = fmaf(qa[i], ka[j], acc[i][j]);
        }

        const bool diag = (kt == qt);
        float alpha[4];
#pragma unroll
        for (int i = 0; i < 4; i++) {
            const int qrow = q0 + (ty << 2) + i;
            float tmp[4];
#pragma unroll
            for (int j = 0; j < 4; j++) {
                float s = acc[i][j] * scale;
                if (diag && (k0 + (tx << 2) + j > qrow)) s = -1.0e30f;
                tmp[j] = s;
            }
            float rm = fmaxf(fmaxf(tmp[0], tmp[1]), fmaxf(tmp[2], tmp[3]));
            rm = fmaxf(rm, __shfl_xor_sync(0xffffffffu, rm, 1, 16));
            rm = fmaxf(rm, __shfl_xor_sync(0xffffffffu, rm, 2, 16));
            rm = fmaxf(rm, __shfl_xor_sync(0xffffffffu, rm, 4, 16));
            rm = fmaxf(rm, __shfl_xor_sync(0xffffffffu, rm, 8, 16));
            float m_new = fmaxf(m_prev[i], rm);
            float al = expf(m_prev[i] - m_new);
            float rs = 0.f;
#pragma unroll
            for (int j = 0; j < 4; j++) {
                float p = expf(tmp[j] - m_new);
                tmp[j] = p;
                rs += p;
            }
            rs += __shfl_xor_sync(0xffffffffu, rs, 1, 16);
            rs += __shfl_xor_sync(0xffffffffu, rs, 2, 16);
            rs += __shfl_xor_sync(0xffffffffu, rs, 4, 16);
            rs += __shfl_xor_sync(0xffffffffu, rs, 8, 16);
            l_run[i]  = l_run[i] * al + rs;
            m_prev[i] = m_new;
            alpha[i]  = al;
            *(float4*)&Ps[(((ty << 2) + i) << 6) + (tx << 2)] =
                make_float4(tmp[0], tmp[1], tmp[2], tmp[3]);
        }
        __syncthreads();

#pragma unroll
        for (int i = 0; i < 4; i++)
#pragma unroll
            for (int j = 0; j < 8; j++) o[i][j] *= alpha[i];

#pragma unroll 4
        for (int k = 0; k < 64; k++) {
            float pv[4];
#pragma unroll
            for (int i = 0; i < 4; i++) pv[i] = Ps[(((ty << 2) + i) << 6) + k];
            float4 v0 = *(const float4*)&Vs[k * 128 + (tx << 3)];
            float4 v1 = *(const float4*)&Vs[k * 128 + (tx << 3) + 4];
            float vv[8] = {v0.x, v0.y, v0.z, v0.w, v1.x, v1.y, v1.z, v1.w};
#pragma unroll
            for (int i = 0; i < 4; i++)
#pragma unroll
                for (int j = 0; j < 8; j++)
                    o[i][j] = fmaf(pv[i], vv[j], o[i][j]);
        }
    }

    // Normalize; write hi/lo bf16 (GEMM2 operand A)
#pragma unroll
    for (int i = 0; i < 4; i++) {
        float inv = 1.0f / l_run[i];
        long row = (long)(b * SEQ + q0 + (ty << 2) + i);
        long off = row * HID + h * HD + (tx << 3);
#pragma unroll
        for (int j = 0; j < 8; j++) {
            float v = o[i][j] * inv;
            __nv_bfloat16 hb = __float2bfloat16(v);
            g_attn_hi[off + j] = hb;
            g_attn_lo[off + j] = __float2bfloat16(v - __bfloat162float(hb));
        }
    }
}

// ---------------------------------------------------------------------------
// Launch: splits -> QKV HMMA-GEMM -> RoPE -> flash -> O HMMA-GEMM
// ---------------------------------------------------------------------------
extern "C" void kernel_launch(void* const* d_in, const int* in_sizes, int n_in,
                              void* d_out, int out_size) {
    const int*   positions = (const int*)d_in[0];
    const float* hidden    = (const float*)d_in[1];
    const float* w_qkv     = (const float*)d_in[2];
    const float* w_o       = (const float*)d_in[3];
    float*       out       = (float*)d_out;

    static __nv_bfloat16 *hid_hi, *hid_lo, *wqT_hi, *wqT_lo, *woT_hi, *woT_lo;
    static __nv_bfloat16 *attn_hi, *attn_lo;
    static float* qkv;
    static bool init = false;
    if (!init) {
        cudaGetSymbolAddress((void**)&hid_hi,  g_hid_hi);
        cudaGetSymbolAddress((void**)&hid_lo,  g_hid_lo);
        cudaGetSymbolAddress((void**)&wqT_hi,  g_wqkvT_hi);
        cudaGetSymbolAddress((void**)&wqT_lo,  g_wqkvT_lo);
        cudaGetSymbolAddress((void**)&woT_hi,  g_woT_hi);
        cudaGetSymbolAddress((void**)&woT_lo,  g_woT_lo);
        cudaGetSymbolAddress((void**)&attn_hi, g_attn_hi);
        cudaGetSymbolAddress((void**)&attn_lo, g_attn_lo);
        cudaGetSymbolAddress((void**)&qkv,     g_qkv);
        cudaFuncSetAttribute(gemm_mma3, cudaFuncAttributeMaxDynamicSharedMemorySize,
                             NSTAGE * STAGE_BYTES);
        cudaFuncSetAttribute(flash_attn, cudaFuncAttributeMaxDynamicSharedMemorySize, 114688);
        init = true;
    }

    // Split inputs to bf16 hi/lo (weights transposed to [N, K])
    {
        int n4 = BS_ROWS * HID / 4;
        split_act<<<(n4 + 255) / 256, 256>>>(hidden, hid_hi, hid_lo, n4);
    }
    split_T<<<dim3(QKV_N / 32, HID / 32), dim3(32, 32)>>>(w_qkv, wqT_hi, wqT_lo, HID, QKV_N);
    split_T<<<dim3(HID / 32, HID / 32), dim3(32, 32)>>>(w_o, woT_hi, woT_lo, HID, HID);

    // QKV projection: [4096,4096] @ [4096,6144] -> g_qkv (f32)
    gemm_mma3<<<dim3(QKV_N / 128, BS_ROWS / 128), 512, NSTAGE * STAGE_BYTES>>>(
        hid_hi, hid_lo, wqT_hi, wqT_lo, qkv, QKV_N, HID);

    const int tot = BS_ROWS * (NQH + NKV) * 64;
    rope_kernel<<<(tot + 255) / 256, 256>>>(positions);

    flash_attn<<<dim3(SEQ / 64, NQH, BATCH), 256, 114688>>>();

    // Output projection: [4096,4096] @ [4096,4096] -> out
    gemm_mma3<<<dim3(HID / 128, BS_ROWS / 128), 512, NSTAGE * STAGE_BYTES>>>(
        attn_hi, attn_lo, woT_hi, woT_lo, out, HID, HID);
}